// round 10
// baseline (speedup 1.0000x reference)
#include <cuda_runtime.h>

#define H 512
#define W 512
#define NB 32

#define SQRT_APPROX(d, a) \
    asm("sqrt.approx.f32 %0, %1;" : "=f"(d) : "f"(a))

// R6 per-thread code extended to 2 output rows per thread.
// Block = 256 threads = 8 warps: warps 0-3 cover rows (h0,h0+1) full width,
// warps 4-7 cover rows (h0+2,h0+3). Each thread loads 4 rows (h-1..h+2,
// independent LDG.128 -> MLP 4) and produces 2 rows of 4 px.
// Stores remain contiguous full-row bursts. grid = (H/4, NB).
__global__ __launch_bounds__(256) void sqdiff_mag_kernel(
    const float* __restrict__ x, float* __restrict__ out)
{
    int lane  = threadIdx.x & 31;
    int warp  = threadIdx.x >> 5;          // 0..7
    int pair  = warp >> 2;                 // 0..1 (which row pair)
    int strip = warp & 3;                  // 0..3 column strip

    int h = (blockIdx.x << 2) + (pair << 1);   // first of 2 output rows
    int n = blockIdx.y;

    int wbase = strip << 7;
    int w     = wbase + (lane << 2);

    const size_t plane = (size_t)H * W;
    const float* g = x + ((size_t)n * 3 + 1) * plane;   // channel 1

    // rows h-1, h, h+1, h+2 as cols [w-1 .. w+4]
    float r[4][6];

    #define LOAD_ROW(j, hh)                                                    \
    {                                                                          \
        const float* p = g + (size_t)(hh) * W + w;                             \
        float4 v = *reinterpret_cast<const float4*>(p);                        \
        r[j][1] = v.x; r[j][2] = v.y; r[j][3] = v.z; r[j][4] = v.w;            \
        float lft = __shfl_up_sync(0xffffffffu, v.w, 1);                       \
        float rgt = __shfl_down_sync(0xffffffffu, v.x, 1);                     \
        if (lane == 0)  lft = (wbase > 0)       ? __ldg(p - 1) : 0.0f;         \
        if (lane == 31) rgt = (wbase + 128 < W) ? __ldg(p + 4) : 0.0f;         \
        r[j][0] = lft; r[j][5] = rgt;                                          \
    }

    LOAD_ROW(1, h)
    LOAD_ROW(2, h + 1)
    if (h > 0) {
        LOAD_ROW(0, h - 1)
    } else {
        #pragma unroll
        for (int i = 0; i < 6; i++) r[0][i] = 0.0f;
    }
    if (h + 2 < H) {
        LOAD_ROW(3, h + 2)
    } else {
        #pragma unroll
        for (int i = 0; i < 6; i++) r[3][i] = 0.0f;
    }
    #undef LOAD_ROW

    float* ob = out + (size_t)n * 3 * plane + (size_t)h * W + w;

    #pragma unroll
    for (int rr = 0; rr < 2; rr++) {
        float4 res;
        float* resp = reinterpret_cast<float*>(&res);
        #pragma unroll
        for (int i = 0; i < 4; i++) {
            float c  = r[rr + 1][i + 1];
            float d0 = c - r[rr + 1][i + 2];
            float d1 = c - r[rr + 1][i];
            float d2 = c - r[rr + 2][i + 1];
            float d3 = c - r[rr][i + 1];
            float d4 = c - r[rr + 2][i + 2];
            float d5 = c - r[rr + 2][i];
            float d6 = c - r[rr][i + 2];
            float d7 = c - r[rr][i];
            float s = d0 * d0;
            s = fmaf(d1, d1, s);
            s = fmaf(d2, d2, s);
            s = fmaf(d3, d3, s);
            s = fmaf(d4, d4, s);
            s = fmaf(d5, d5, s);
            s = fmaf(d6, d6, s);
            s = fmaf(d7, d7, s);
            SQRT_APPROX(resp[i], s);
        }
        float* o = ob + (size_t)rr * W;
        __stcs(reinterpret_cast<float4*>(o),             res);
        __stcs(reinterpret_cast<float4*>(o + plane),     res);
        __stcs(reinterpret_cast<float4*>(o + 2 * plane), res);
    }
}

extern "C" void kernel_launch(void* const* d_in, const int* in_sizes, int n_in,
                              void* d_out, int out_size)
{
    const float* x = (const float*)d_in[0];
    float* out = (float*)d_out;

    dim3 grid(H / 4, NB);   // 128 x 32 = 4096 CTAs of 256 threads
    sqdiff_mag_kernel<<<grid, 256>>>(x, out);
}